// round 3
// baseline (speedup 1.0000x reference)
#include <cuda_runtime.h>
#include <math.h>
#include <stdint.h>

#define LLATT 16                 // lattice side
#define UU    512
#define CL    8                  // cluster size (CTAs)
#define NCLUS 16                 // clusters
#define NBP   8                  // batch pairs per cluster (16 batches)
#define KS    128                // K-rows per CTA (1024 / 8)
#define USL   64                 // output-unit slice per owner CTA (512 / 8)
#define NTHR  256

typedef unsigned long long ull;

struct SM {
    ull   h_in[KS][NBP];             // ranks 0-3: their slice of current h   (8 KB)
    ull   states[LLATT][KS][NBP];    // ranks 4-7: their slice of prev row    (128 KB)
    ull   inbox[CL][NBP][USL];       // partial sums from 8 source CTAs       (32 KB)
    ull   zbox[CL][NBP][2];          // logit partials -> CTA 0               (1 KB)
    ull   hbuf[NBP][USL];            // owner's fresh h slice (for logits)    (4 KB)
    float winh[2][UU];               // (4 KB)
    float winv[2][UU];               // (4 KB)
    float bcarry[UU];                // (2 KB)
    float wout[UU][2];               // (4 KB)
    float logp[16];
    float bout0, bout1;
    int   xs[16][LLATT * LLATT];     // spins for this cluster's batches      (16 KB)
};

__device__ __forceinline__ ull pk2(float lo, float hi) {
    ull r; asm("mov.b64 %0, {%1, %2};" : "=l"(r) : "f"(lo), "f"(hi)); return r;
}
__device__ __forceinline__ void upk2(ull v, float& lo, float& hi) {
    asm("mov.b64 {%0, %1}, %2;" : "=f"(lo), "=f"(hi) : "l"(v));
}
__device__ __forceinline__ void fma2(ull& acc, ull a, ull b) {
    asm("fma.rn.f32x2 %0, %1, %2, %0;" : "+l"(acc) : "l"(a), "l"(b));
}
__device__ __forceinline__ ull add2(ull a, ull b) {
    ull r; asm("add.rn.f32x2 %0, %1, %2;" : "=l"(r) : "l"(a), "l"(b)); return r;
}
__device__ __forceinline__ uint32_t smem_u32(const void* p) {
    return (uint32_t)__cvta_generic_to_shared(p);
}
__device__ __forceinline__ uint32_t mapa_rank(uint32_t laddr, uint32_t rank) {
    uint32_t r;
    asm("mapa.shared::cluster.u32 %0, %1, %2;" : "=r"(r) : "r"(laddr), "r"(rank));
    return r;
}
__device__ __forceinline__ void st_cl64(uint32_t addr, ull v) {
    asm volatile("st.shared::cluster.b64 [%0], %1;" :: "r"(addr), "l"(v) : "memory");
}
#define CLUSTER_ARRIVE() asm volatile("barrier.cluster.arrive.aligned;" ::: "memory")
#define CLUSTER_WAIT()   asm volatile("barrier.cluster.wait.aligned;"   ::: "memory")

__global__ void __launch_bounds__(NTHR, 1) __cluster_dims__(CL, 1, 1)
rnn2d_kernel(const int* __restrict__ x,
             const float* __restrict__ Winh, const float* __restrict__ Winv,
             const float* __restrict__ Wch,  const float* __restrict__ bch,
             const float* __restrict__ Wcv,
             const float* __restrict__ Wout, const float* __restrict__ bout,
             float* __restrict__ out)
{
    extern __shared__ char smraw[];
    SM& sm = *reinterpret_cast<SM*>(smraw);
    const int tid = threadIdx.x;
    uint32_t rank;
    asm("mov.u32 %0, %%cluster_ctarank;" : "=r"(rank));
    const int cl = blockIdx.x >> 3;       // cluster id (batch group)

    // ---------------- prologue ----------------
    for (int idx = tid; idx < 2 * UU; idx += NTHR) {
        ((float*)sm.winh)[idx] = Winh[idx];
        ((float*)sm.winv)[idx] = Winv[idx];
        ((float*)sm.wout)[idx] = Wout[idx];
    }
    for (int idx = tid; idx < UU; idx += NTHR) sm.bcarry[idx] = bch[idx];
    for (int idx = tid; idx < 16 * LLATT * LLATT; idx += NTHR)
        ((int*)sm.xs)[idx] = x[cl * 16 * LLATT * LLATT + idx];
    {   // zero h_in and states
        ull* hz = &sm.h_in[0][0];
        for (int idx = tid; idx < KS * NBP; idx += NTHR) hz[idx] = 0ull;
        ull* st = &sm.states[0][0][0];
        for (int idx = tid; idx < LLATT * KS * NBP; idx += NTHR) st[idx] = 0ull;
    }
    if (tid < 16) sm.logp[tid] = 0.f;
    if (tid == 0) { sm.bout0 = bout[0]; sm.bout1 = bout[1]; }
    __syncthreads();
    CLUSTER_ARRIVE(); CLUSTER_WAIT();

    // weight slice for this CTA: rows [r0, r0+KS) of Wch (ranks 0-3) or Wcv (4-7)
    const float* Wbase = (rank < 4) ? (Wch + (int)rank * KS * UU)
                                    : (Wcv + ((int)rank - 4) * KS * UU);
    const float2* __restrict__ Wg = reinterpret_cast<const float2*>(Wbase);

    // precomputed DSMEM addresses
    const uint32_t inbox_rem =                       // my slice in owner (tid>>5)'s inbox
        mapa_rank(smem_u32(&sm.inbox[rank][0][0]), (uint32_t)(tid >> 5));
    const int trg = (int)rank >> 1;                  // h-CTA fed by my owner slice
    const uint32_t hin_rem  = mapa_rank(smem_u32(&sm.h_in[0][0]), (uint32_t)trg);
    const uint32_t st_rem   = mapa_rank(smem_u32(&sm.states[0][0][0]), (uint32_t)(4 + trg));
    const uint32_t zbox_rem = mapa_rank(smem_u32(&sm.zbox[rank][0][0]), 0u);

    const int ul0 = (tid & 31) * 2;                  // unit offset inside owner slice

    for (int i = 0; i < LLATT; ++i) {
        const int d = (i & 1) ? -1 : 1;
        for (int j = 0; j < LLATT; ++j) {
            const int c = (d == 1) ? j : (LLATT - 1 - j);

            if (j == 0) {                            // h resets at each row start
                if (rank < 4) {
                    ull* hz = &sm.h_in[0][0];
                    for (int idx = tid; idx < KS * NBP; idx += NTHR) hz[idx] = 0ull;
                }
                __syncthreads();
            }

            // ---- compute partial GEMV over my K-slice ----
            const ull (*inp)[NBP] = (rank < 4) ? sm.h_in : sm.states[c];
            ull acc0[NBP], acc1[NBP];
#pragma unroll
            for (int p = 0; p < NBP; ++p) { acc0[p] = 0ull; acc1[p] = 0ull; }
#pragma unroll 1
            for (int kk = 0; kk < KS; kk += 8) {
                float2 w[8];
#pragma unroll
                for (int t = 0; t < 8; ++t) w[t] = Wg[(kk + t) * 256 + tid];
#pragma unroll
                for (int t = 0; t < 8; ++t) {
                    const ull wx = pk2(w[t].x, w[t].x);
                    const ull wy = pk2(w[t].y, w[t].y);
                    const ull* iv = inp[kk + t];
#pragma unroll
                    for (int p = 0; p < NBP; ++p) {
                        const ull v = iv[p];
                        fma2(acc0[p], v, wx);
                        fma2(acc1[p], v, wy);
                    }
                }
            }
            // scatter partials to owners' inboxes (owner = tid>>5, units ul0,ul0+1)
#pragma unroll
            for (int p = 0; p < NBP; ++p) {
                st_cl64(inbox_rem + (uint32_t)((p * USL + ul0) * 8),     acc0[p]);
                st_cl64(inbox_rem + (uint32_t)((p * USL + ul0 + 1) * 8), acc1[p]);
            }
            CLUSTER_ARRIVE(); CLUSTER_WAIT();        // barrier 1

            // ---- owner: reduce + bias + one-hot + elu, distribute new h ----
#pragma unroll
            for (int s2 = 0; s2 < 2; ++s2) {
                const int s = tid + s2 * 256;        // 512 slots = 8 pairs x 64 units
                const int p = s >> 6, ul = s & 63;
                ull a = sm.inbox[0][p][ul];
#pragma unroll
                for (int src = 1; src < CL; ++src) a = add2(a, sm.inbox[src][p][ul]);
                float v0, v1; upk2(a, v0, v1);
                const int ug = (int)rank * USL + ul;
                const float base = sm.bcarry[ug];
                v0 += base; v1 += base;
                const int b0 = 2 * p, b1 = 2 * p + 1;
                if (j > 0) {
                    const int cp = c - d;
                    v0 += sm.winh[sm.xs[b0][i * LLATT + cp]][ug];
                    v1 += sm.winh[sm.xs[b1][i * LLATT + cp]][ug];
                }
                if (i > 0) {
                    v0 += sm.winv[sm.xs[b0][(i - 1) * LLATT + c]][ug];
                    v1 += sm.winv[sm.xs[b1][(i - 1) * LLATT + c]][ug];
                }
                v0 = v0 > 0.f ? v0 : expm1f(v0);
                v1 = v1 > 0.f ? v1 : expm1f(v1);
                const ull hv = pk2(v0, v1);
                sm.hbuf[p][ul] = hv;
                const int kl = (((int)rank & 1) << 6) | ul;   // row inside target slice
                st_cl64(hin_rem + (uint32_t)((kl * NBP + p) * 8), hv);
                st_cl64(st_rem + (uint32_t)(((c * KS + kl) * NBP + p) * 8), hv);
            }
            __syncthreads();

            // ---- partial logits over my 64 units: warp w = batch pair w ----
            {
                const int w = tid >> 5, lane = tid & 31;
                float z00 = 0.f, z01 = 0.f, z10 = 0.f, z11 = 0.f;
#pragma unroll
                for (int t = 0; t < 2; ++t) {
                    const int u = lane + t * 32;
                    float h0, h1; upk2(sm.hbuf[w][u], h0, h1);
                    const int ug = (int)rank * USL + u;
                    const float w0 = sm.wout[ug][0], w1 = sm.wout[ug][1];
                    z00 += h0 * w0; z01 += h1 * w0;
                    z10 += h0 * w1; z11 += h1 * w1;
                }
#pragma unroll
                for (int off = 16; off; off >>= 1) {
                    z00 += __shfl_down_sync(0xffffffffu, z00, off);
                    z01 += __shfl_down_sync(0xffffffffu, z01, off);
                    z10 += __shfl_down_sync(0xffffffffu, z10, off);
                    z11 += __shfl_down_sync(0xffffffffu, z11, off);
                }
                if (lane == 0) {
                    st_cl64(zbox_rem + (uint32_t)((w * 2 + 0) * 8), pk2(z00, z01));
                    st_cl64(zbox_rem + (uint32_t)((w * 2 + 1) * 8), pk2(z10, z11));
                }
            }
            CLUSTER_ARRIVE(); CLUSTER_WAIT();        // barrier 2

            // ---- CTA 0: accumulate log-probabilities ----
            if (rank == 0 && tid < 16) {
                const int p = tid >> 1, l = tid & 1;
                float z0 = sm.bout0, z1 = sm.bout1;
#pragma unroll
                for (int src = 0; src < CL; ++src) {
                    float a, b;
                    upk2(sm.zbox[src][p][0], a, b); z0 += l ? b : a;
                    upk2(sm.zbox[src][p][1], a, b); z1 += l ? b : a;
                }
                const int s = sm.xs[tid][i * LLATT + c];
                const float m = fmaxf(z0, z1);
                const float lse = m + logf(expf(z0 - m) + expf(z1 - m));
                sm.logp[tid] += (s ? z1 : z0) - lse;
            }
        }
    }
    __syncthreads();
    if (rank == 0 && tid < 16) out[cl * 16 + tid] = sm.logp[tid];
}

extern "C" void kernel_launch(void* const* d_in, const int* in_sizes, int n_in,
                              void* d_out, int out_size)
{
    const int*   x    = (const int*)d_in[0];
    const float* Winh = (const float*)d_in[1];
    const float* Winv = (const float*)d_in[2];
    const float* Wch  = (const float*)d_in[3];
    const float* bch  = (const float*)d_in[4];
    const float* Wcv  = (const float*)d_in[5];
    const float* Wout = (const float*)d_in[6];
    const float* bout = (const float*)d_in[7];
    float* out = (float*)d_out;

    const int smem = (int)sizeof(SM);
    cudaFuncSetAttribute(rnn2d_kernel,
                         cudaFuncAttributeMaxDynamicSharedMemorySize, smem);
    rnn2d_kernel<<<NCLUS * CL, NTHR, smem>>>(x, Winh, Winv, Wch, bch, Wcv,
                                             Wout, bout, out);
}

// round 4
// speedup vs baseline: 1.6854x; 1.6854x over previous
#include <cuda_runtime.h>
#include <math.h>
#include <stdint.h>

#define LLATT 16
#define UU    512
#define NB    4            // batches per cluster (group)
#define CL    2            // CTAs per cluster, unit-split
#define USL   256          // units per CTA
#define NTHR  256
#define NGRP  (256 / NB)   // 64 groups
#define NCTA  (NGRP * CL)  // 128 CTAs

typedef unsigned long long ull;

struct SM {
    ull   hbuf[2][UU][2];        // double-buffered full h [buf][u][bpair]  16 KB
    ull   states[8][UU][2];      // last 8 scan-positions' h (full units)   64 KB
    ull   vrow[LLATT][USL][2];   // vertical terms per column, unit slice   64 KB
    ull   pred[128][2][2];       // k-half partials [tu][unit][bpair]        4 KB
    float winh[2][UU];
    float winv[2][UU];
    float wout[UU][2];
    float bcarry[UU];
    float z[NB][2];
    float logp[NB];
    float bout0, bout1;
    int   xs[NB][LLATT * LLATT];
    ull   bar1;                  // per-cell cluster mbarrier
};

__device__ __forceinline__ ull pk2(float lo, float hi) {
    ull r; asm("mov.b64 %0, {%1, %2};" : "=l"(r) : "f"(lo), "f"(hi)); return r;
}
__device__ __forceinline__ void upk2(ull v, float& lo, float& hi) {
    asm("mov.b64 {%0, %1}, %2;" : "=f"(lo), "=f"(hi) : "l"(v));
}
__device__ __forceinline__ void fma2(ull& acc, ull a, ull b) {
    asm("fma.rn.f32x2 %0, %1, %2, %0;" : "+l"(acc) : "l"(a), "l"(b));
}
__device__ __forceinline__ uint32_t smem_u32(const void* p) {
    return (uint32_t)__cvta_generic_to_shared(p);
}
__device__ __forceinline__ uint32_t mapa_rank(uint32_t a, uint32_t r) {
    uint32_t o; asm("mapa.shared::cluster.u32 %0, %1, %2;" : "=r"(o) : "r"(a), "r"(r));
    return o;
}
__device__ __forceinline__ void st_cl64(uint32_t addr, ull v) {
    asm volatile("st.shared::cluster.b64 [%0], %1;" :: "r"(addr), "l"(v) : "memory");
}
__device__ __forceinline__ void mbar_init(uint32_t addr, uint32_t cnt) {
    asm volatile("mbarrier.init.shared.b64 [%0], %1;" :: "r"(addr), "r"(cnt) : "memory");
}
__device__ __forceinline__ void mbar_arrive_remote(uint32_t addr) {
    asm volatile("mbarrier.arrive.release.cluster.shared::cluster.b64 _, [%0];"
                 :: "r"(addr) : "memory");
}
__device__ __forceinline__ void mbar_wait_parity(uint32_t addr, uint32_t parity) {
    asm volatile(
        "{\n\t.reg .pred P;\n\t"
        "WLP_%=:\n\t"
        "mbarrier.try_wait.parity.acquire.cluster.shared::cta.b64 P, [%0], %1, 0x989680;\n\t"
        "@P bra.uni WDN_%=;\n\t"
        "bra.uni WLP_%=;\n\t"
        "WDN_%=:\n\t}"
        :: "r"(addr), "r"(parity) : "memory");
}
#define CLUSTER_ARRIVE() asm volatile("barrier.cluster.arrive.aligned;" ::: "memory")
#define CLUSTER_WAIT()   asm volatile("barrier.cluster.wait.aligned;"   ::: "memory")

__global__ void __launch_bounds__(NTHR, 1) __cluster_dims__(CL, 1, 1)
rnn2d_kernel(const int* __restrict__ x,
             const float* __restrict__ Winh, const float* __restrict__ Winv,
             const float* __restrict__ Wch,  const float* __restrict__ bch,
             const float* __restrict__ Wcv,
             const float* __restrict__ Wout, const float* __restrict__ bout,
             float* __restrict__ out)
{
    extern __shared__ char smraw[];
    SM& sm = *reinterpret_cast<SM*>(smraw);
    const int tid = threadIdx.x;
    uint32_t rank;
    asm("mov.u32 %0, %%cluster_ctarank;" : "=r"(rank));
    const int grp = blockIdx.x >> 1;

    // ---------------- prologue ----------------
    for (int idx = tid; idx < 2 * UU; idx += NTHR) {
        ((float*)sm.winh)[idx] = Winh[idx];
        ((float*)sm.winv)[idx] = Winv[idx];
        ((float*)sm.wout)[idx] = Wout[idx];
    }
    for (int idx = tid; idx < UU; idx += NTHR) sm.bcarry[idx] = bch[idx];
    for (int idx = tid; idx < NB * LLATT * LLATT; idx += NTHR)
        ((int*)sm.xs)[idx] = x[grp * NB * LLATT * LLATT + idx];
    {   // zero vrow (row 0 reads it)
        ull* vz = &sm.vrow[0][0][0];
        for (int idx = tid; idx < LLATT * USL * 2; idx += NTHR) vz[idx] = 0ull;
    }
    if (tid < NB) sm.logp[tid] = 0.f;
    if (tid == 0) {
        sm.bout0 = bout[0]; sm.bout1 = bout[1];
        mbar_init(smem_u32(&sm.bar1), 128);   // 128 writer arrivals from peer
    }
    __syncthreads();
    CLUSTER_ARRIVE(); CLUSTER_WAIT();          // publish mbarrier init

    const int khalf = tid >> 7;                // 0: k 0-255 (writers), 1: k 256-511
    const int tu    = tid & 127;
    const int ug0   = (int)rank * USL + 2 * tu;  // global unit pair

    const uint32_t bar_loc  = smem_u32(&sm.bar1);
    const uint32_t bar_rem  = mapa_rank(bar_loc, rank ^ 1u);
    const uint32_t hbuf_rem = mapa_rank(smem_u32(&sm.hbuf[0][0][0]), rank ^ 1u);
    const uint32_t st_rem   = mapa_rank(smem_u32(&sm.states[0][0][0]), rank ^ 1u);

    const float2* __restrict__ WchP =
        reinterpret_cast<const float2*>(Wch + (size_t)(khalf * 256) * UU + ug0);
    const float4* __restrict__ WcvP =
        reinterpret_cast<const float4*>(Wcv + (int)rank * USL + (tid & 63) * 4);

    int n = 0;
    for (int i = 0; i < LLATT; ++i) {
        const int d = (i & 1) ? -1 : 1;
        for (int j = 0; j < LLATT; ++j, ++n) {
            const int c   = (d == 1) ? j : (LLATT - 1 - j);
            const int buf = n & 1;

            // ---- half-row vertical GEMM events (31 total) ----
            if ((j == 8 && i < 15) || (j == 0 && i > 0)) {
                __syncthreads();
                const int i_src = (j == 8) ? i : i - 1;
                const int p0    = (j == 8) ? 0 : 8;
                const int uw = tid & 63, cw = tid >> 6;
                const int p1 = p0 + cw * 2, p2 = p1 + 1;
                const int s1 = p1 & 7, s2 = p2 & 7;
                const int c1 = (i_src & 1) ? 15 - p1 : p1;
                const int c2 = (i_src & 1) ? 15 - p2 : p2;
                const int lu = uw * 4;
                ull A[2][4][2];
#pragma unroll
                for (int p = 0; p < 2; ++p)
#pragma unroll
                    for (int q = 0; q < 4; ++q) { A[p][q][0] = 0ull; A[p][q][1] = 0ull; }
#pragma unroll 1
                for (int k = 0; k < UU; k += 4) {
                    float4 w[4];
#pragma unroll
                    for (int q = 0; q < 4; ++q) w[q] = WcvP[(k + q) * 128];
#pragma unroll
                    for (int q = 0; q < 4; ++q) {
                        const ull sa0 = sm.states[s1][k + q][0];
                        const ull sa1 = sm.states[s1][k + q][1];
                        const ull sb0 = sm.states[s2][k + q][0];
                        const ull sb1 = sm.states[s2][k + q][1];
                        const ull wx = pk2(w[q].x, w[q].x);
                        const ull wy = pk2(w[q].y, w[q].y);
                        const ull wz = pk2(w[q].z, w[q].z);
                        const ull ww = pk2(w[q].w, w[q].w);
                        fma2(A[0][0][0], sa0, wx); fma2(A[0][0][1], sa1, wx);
                        fma2(A[0][1][0], sa0, wy); fma2(A[0][1][1], sa1, wy);
                        fma2(A[0][2][0], sa0, wz); fma2(A[0][2][1], sa1, wz);
                        fma2(A[0][3][0], sa0, ww); fma2(A[0][3][1], sa1, ww);
                        fma2(A[1][0][0], sb0, wx); fma2(A[1][0][1], sb1, wx);
                        fma2(A[1][1][0], sb0, wy); fma2(A[1][1][1], sb1, wy);
                        fma2(A[1][2][0], sb0, wz); fma2(A[1][2][1], sb1, wz);
                        fma2(A[1][3][0], sb0, ww); fma2(A[1][3][1], sb1, ww);
                    }
                }
#pragma unroll
                for (int q = 0; q < 4; ++q) {
                    sm.vrow[c1][lu + q][0] = A[0][q][0];
                    sm.vrow[c1][lu + q][1] = A[0][q][1];
                    sm.vrow[c2][lu + q][0] = A[1][q][0];
                    sm.vrow[c2][lu + q][1] = A[1][q][1];
                }
                __syncthreads();
                CLUSTER_ARRIVE(); CLUSTER_WAIT();   // fence GEMM vs slot reuse
            }

            // ---- h @ W_carry_h over my k-half (skip at row start) ----
            ull a00 = 0ull, a01 = 0ull, a10 = 0ull, a11 = 0ull;
            if (j > 0) {
                const int kbase = khalf * 256;
#pragma unroll 1
                for (int kk = 0; kk < 256; kk += 8) {
                    float2 w[8];
#pragma unroll
                    for (int q = 0; q < 8; ++q) w[q] = WchP[(kk + q) * 256];
#pragma unroll
                    for (int q = 0; q < 8; ++q) {
                        const int k = kbase + kk + q;
                        const ull h0 = sm.hbuf[buf ^ 1][k][0];
                        const ull h1 = sm.hbuf[buf ^ 1][k][1];
                        const ull wx = pk2(w[q].x, w[q].x);
                        const ull wy = pk2(w[q].y, w[q].y);
                        fma2(a00, h0, wx); fma2(a01, h1, wx);
                        fma2(a10, h0, wy); fma2(a11, h1, wy);
                    }
                }
            }
            if (khalf == 1) {
                sm.pred[tu][0][0] = a00; sm.pred[tu][0][1] = a01;
                sm.pred[tu][1][0] = a10; sm.pred[tu][1][1] = a11;
            }
            __syncthreads();   // S1: partials visible

            // ---- reduce + inputs + elu + distribute (threads 0-127) ----
            if (khalf == 0) {
                float v[2][4];
                upk2(a00, v[0][0], v[0][1]); upk2(a01, v[0][2], v[0][3]);
                upk2(a10, v[1][0], v[1][1]); upk2(a11, v[1][2], v[1][3]);
                if (j > 0) {
#pragma unroll
                    for (int q = 0; q < 2; ++q) {
                        float p0f, p1f;
                        upk2(sm.pred[tu][q][0], p0f, p1f);
                        v[q][0] += p0f; v[q][1] += p1f;
                        upk2(sm.pred[tu][q][1], p0f, p1f);
                        v[q][2] += p0f; v[q][3] += p1f;
                    }
                }
                if (i > 0) {
#pragma unroll
                    for (int q = 0; q < 2; ++q) {
                        float p0f, p1f;
                        upk2(sm.vrow[c][2 * tu + q][0], p0f, p1f);
                        v[q][0] += p0f; v[q][1] += p1f;
                        upk2(sm.vrow[c][2 * tu + q][1], p0f, p1f);
                        v[q][2] += p0f; v[q][3] += p1f;
                    }
                }
                int sh[NB], sv[NB];
                if (j > 0) {
                    const int cp = c - d;
#pragma unroll
                    for (int b = 0; b < NB; ++b) sh[b] = sm.xs[b][i * LLATT + cp];
                }
                if (i > 0) {
#pragma unroll
                    for (int b = 0; b < NB; ++b) sv[b] = sm.xs[b][(i - 1) * LLATT + c];
                }
                const int slot = j & 7;
#pragma unroll
                for (int q = 0; q < 2; ++q) {
                    const int u = ug0 + q;
                    const float base = sm.bcarry[u];
#pragma unroll
                    for (int b = 0; b < NB; ++b) {
                        float t = v[q][b] + base;
                        if (j > 0) t += sm.winh[sh[b]][u];
                        if (i > 0) t += sm.winv[sv[b]][u];
                        v[q][b] = t > 0.f ? t : expm1f(t);
                    }
                    const ull e0 = pk2(v[q][0], v[q][1]);
                    const ull e1 = pk2(v[q][2], v[q][3]);
                    sm.hbuf[buf][u][0] = e0;   sm.hbuf[buf][u][1] = e1;
                    sm.states[slot][u][0] = e0; sm.states[slot][u][1] = e1;
                    const uint32_t ho = (uint32_t)(((buf * UU + u) * 2) * 8);
                    st_cl64(hbuf_rem + ho,     e0);
                    st_cl64(hbuf_rem + ho + 8, e1);
                    const uint32_t so = (uint32_t)(((slot * UU + u) * 2) * 8);
                    st_cl64(st_rem + so,     e0);
                    st_cl64(st_rem + so + 8, e1);
                }
                mbar_arrive_remote(bar_rem);
            }
            __syncthreads();              // S2: local h visible
            mbar_wait_parity(bar_loc, (uint32_t)(n & 1));  // peer slice arrived

            // ---- logits: warp w -> (batch w>>1, class w&1), local full h ----
            {
                const int w = tid >> 5, lane = tid & 31;
                const int b = w >> 1, dc = w & 1;
                const int bp = b >> 1, hi = b & 1;
                float z = 0.f;
#pragma unroll
                for (int q = 0; q < 16; ++q) {
                    const int u = lane + q * 32;
                    float lo2, hi2;
                    upk2(sm.hbuf[buf][u][bp], lo2, hi2);
                    z += (hi ? hi2 : lo2) * sm.wout[u][dc];
                }
#pragma unroll
                for (int off = 16; off; off >>= 1)
                    z += __shfl_down_sync(0xffffffffu, z, off);
                if (lane == 0) sm.z[b][dc] = z;
            }
            __syncthreads();              // S3
            if (tid < NB) {
                const float z0 = sm.z[tid][0] + sm.bout0;
                const float z1 = sm.z[tid][1] + sm.bout1;
                const int s = sm.xs[tid][i * LLATT + c];
                const float m = fmaxf(z0, z1);
                const float lse = m + logf(expf(z0 - m) + expf(z1 - m));
                sm.logp[tid] += (s ? z1 : z0) - lse;
            }
        }
    }
    __syncthreads();
    if (rank == 0 && tid < NB) out[grp * NB + tid] = sm.logp[tid];
    CLUSTER_ARRIVE(); CLUSTER_WAIT();     // no CTA exits while peer may write DSMEM
}

extern "C" void kernel_launch(void* const* d_in, const int* in_sizes, int n_in,
                              void* d_out, int out_size)
{
    const int*   x    = (const int*)d_in[0];
    const float* Winh = (const float*)d_in[1];
    const float* Winv = (const float*)d_in[2];
    const float* Wch  = (const float*)d_in[3];
    const float* bch  = (const float*)d_in[4];
    const float* Wcv  = (const float*)d_in[5];
    const float* Wout = (const float*)d_in[6];
    const float* bout = (const float*)d_in[7];
    float* out = (float*)d_out;

    const int smem = (int)sizeof(SM);
    cudaFuncSetAttribute(rnn2d_kernel,
                         cudaFuncAttributeMaxDynamicSharedMemorySize, smem);
    rnn2d_kernel<<<NCTA, NTHR, smem>>>(x, Winh, Winv, Wch, bch, Wcv,
                                       Wout, bout, out);
}